// round 4
// baseline (speedup 1.0000x reference)
#include <cuda_runtime.h>
#include <math.h>

#define B 32
#define HH 512
#define WW 512
#define NPIX (HH*WW)          // 262144
#define NTOT (B*NPIX)         // 8388608
#define KRAD 15               // box radius

// Scratch: horizontal box sums of y_target. 33.5 MB.
__device__ float g_Hsum[NTOT];

// Accumulators (zero at module load; Pass-B tail restores zeros every call)
__device__ float g_sum_t[B];
__device__ float g_sum_p[B];
__device__ float g_wsum[B];
__device__ float g_inter[B];
__device__ float g_uni[B];
__device__ float g_qsum[B];
__device__ float g_bce;
__device__ int   g_done;

__device__ __forceinline__ float fsigmoid(float x) {
    return __fdividef(1.f, 1.f + __expf(-x));
}

// -------- Kernel 1: pure streaming stats: sum_t, sum_p (per image), bce ------
// 2048 blocks x 256 thr. 64 blocks per image; 1024 float4 per array per block.
__global__ __launch_bounds__(256) void k_statsA(const float* __restrict__ P,
                                                const float* __restrict__ T) {
    __shared__ float red[3][8];
    const int b     = blockIdx.x >> 6;
    const int chunk = blockIdx.x & 63;
    const float4* t4 = (const float4*)(T + (size_t)b * NPIX) + (size_t)chunk * 1024;
    const float4* p4 = (const float4*)(P + (size_t)b * NPIX) + (size_t)chunk * 1024;

    float st = 0.f, sp = 0.f, sb = 0.f;
    #pragma unroll
    for (int i = 0; i < 4; i++) {
        float4 tv = t4[i * 256 + threadIdx.x];
        float4 pv = p4[i * 256 + threadIdx.x];
        float ts[4] = {tv.x, tv.y, tv.z, tv.w};
        float xs[4] = {pv.x, pv.y, pv.z, pv.w};
        #pragma unroll
        for (int k = 0; k < 4; k++) {
            float t = ts[k], x = xs[k];
            st += t;
            sp += fsigmoid(x);
            sb += fmaxf(x, 0.f) - x * t + __logf(1.f + __expf(-fabsf(x)));
        }
    }
    const int warp = threadIdx.x >> 5, lane = threadIdx.x & 31;
    #pragma unroll
    for (int o = 16; o > 0; o >>= 1) {
        st += __shfl_xor_sync(~0u, st, o);
        sp += __shfl_xor_sync(~0u, sp, o);
        sb += __shfl_xor_sync(~0u, sb, o);
    }
    if (lane == 0) { red[0][warp] = st; red[1][warp] = sp; red[2][warp] = sb; }
    __syncthreads();
    if (threadIdx.x == 0) {
        float a = 0.f, c = 0.f, d = 0.f;
        #pragma unroll
        for (int w = 0; w < 8; w++) { a += red[0][w]; c += red[1][w]; d += red[2][w]; }
        atomicAdd(&g_sum_t[b], a);
        atomicAdd(&g_sum_p[b], c);
        atomicAdd(&g_bce, d);
    }
}

// -------- Kernel 2: horizontal box sums of T -> g_Hsum -----------------------
// 8 warps per block, one warp per row. 2048 blocks cover 16384 rows.
// T should be L2-resident after k_statsA.
__global__ __launch_bounds__(256) void k_hboxA(const float* __restrict__ T) {
    __shared__ __align__(16) float sIn[8][WW];
    __shared__ __align__(16) float sOut[8][WW];

    const int warp = threadIdx.x >> 5;
    const int lane = threadIdx.x & 31;
    const int rowg = blockIdx.x * 8 + warp;

    const float4* t4 = (const float4*)(T + (size_t)rowg * WW);
    #pragma unroll
    for (int i = 0; i < 4; i++)
        ((float4*)sIn[warp])[lane + 32*i] = t4[lane + 32*i];
    __syncwarp();

    // per-lane sliding window over 16 contiguous columns
    const int base = lane * 16;
    float s = 0.f;
    #pragma unroll
    for (int k = base - KRAD; k <= base + KRAD; k++)
        if (k >= 0 && k < WW) s += sIn[warp][k];
    sOut[warp][base] = s;
    #pragma unroll
    for (int j = 1; j < 16; j++) {
        int ka = base + KRAD + j;
        int kr = base - KRAD - 1 + j;
        if (ka < WW) s += sIn[warp][ka];
        if (kr >= 0) s -= sIn[warp][kr];
        sOut[warp][base + j] = s;
    }
    __syncwarp();

    float4* h4 = (float4*)(g_Hsum + (size_t)rowg * WW);
    #pragma unroll
    for (int i = 0; i < 4; i++)
        h4[lane + 32*i] = ((float4*)sOut[warp])[lane + 32*i];
}

// -------- Kernel 3: vertical box + weighted sums + E-measure + finalize ------
// grid 2048 blocks: b = bx>>6, band = (bx>>2)&15 (32 rows), strip = bx&3.
// 128 threads = one column each. Last-finishing block computes the scalar
// output and resets all accumulators for the next graph replay.
__global__ __launch_bounds__(128) void k_passB(const float* __restrict__ P,
                                               const float* __restrict__ T,
                                               float* __restrict__ out) {
    __shared__ float red[4][4];
    __shared__ int s_last;
    const int bx    = blockIdx.x;
    const int b     = bx >> 6;
    const int band  = (bx >> 2) & 15;
    const int strip = bx & 3;
    const int col   = strip * 128 + threadIdx.x;
    const int r0    = band * 32;

    const float* Hb = g_Hsum + (size_t)b * NPIX;
    const float* Tb = T + (size_t)b * NPIX;
    const float* Pb = P + (size_t)b * NPIX;

    const float mean_p = g_sum_p[b] * (1.f / (float)NPIX);
    const float mean_t = g_sum_t[b] * (1.f / (float)NPIX);

    // init vertical running window around r0
    float vsum = 0.f;
    {
        const int lo = max(r0 - KRAD, 0);
        const int hi = min(r0 + KRAD, HH - 1);
        for (int r = lo; r <= hi; r++) vsum += Hb[r * WW + col];
    }

    float a_w = 0.f, a_i = 0.f, a_u = 0.f, a_q = 0.f;
    #pragma unroll 4
    for (int r = r0; r < r0 + 32; r++) {
        float box = vsum * (1.f / 961.f);
        float t = Tb[r * WW + col];
        float x = Pb[r * WW + col];
        float p = fsigmoid(x);
        float w = 1.f + 5.f * fabsf(box - t);
        a_w += w;
        a_i += p * t * w;
        a_u += (p + t) * w;
        float fp = p - mean_p;
        float ft = t - mean_t;
        float efm = __fdividef(2.f * fp * ft + 1e-8f, fp * fp + ft * ft + 1e-8f);
        float q = 1.f + efm;
        a_q += q * q * 0.25f;
        int ra = r + KRAD + 1, rr = r - KRAD;
        if (ra < HH) vsum += Hb[ra * WW + col];
        if (rr >= 0) vsum -= Hb[rr * WW + col];
    }

    const int warp = threadIdx.x >> 5, lane = threadIdx.x & 31;
    #pragma unroll
    for (int o = 16; o > 0; o >>= 1) {
        a_w += __shfl_xor_sync(~0u, a_w, o);
        a_i += __shfl_xor_sync(~0u, a_i, o);
        a_u += __shfl_xor_sync(~0u, a_u, o);
        a_q += __shfl_xor_sync(~0u, a_q, o);
    }
    if (lane == 0) { red[0][warp] = a_w; red[1][warp] = a_i; red[2][warp] = a_u; red[3][warp] = a_q; }
    __syncthreads();
    if (threadIdx.x == 0) {
        float rw = 0.f, ri = 0.f, ru = 0.f, rq = 0.f;
        #pragma unroll
        for (int w = 0; w < 4; w++) { rw += red[0][w]; ri += red[1][w]; ru += red[2][w]; rq += red[3][w]; }
        atomicAdd(&g_wsum[b],  rw);
        atomicAdd(&g_inter[b], ri);
        atomicAdd(&g_uni[b],   ru);
        atomicAdd(&g_qsum[b],  rq);
        __threadfence();
        s_last = (atomicAdd(&g_done, 1) == gridDim.x - 1);
    }
    __syncthreads();

    if (s_last) {
        const int ib = threadIdx.x;   // threads 0..31 handle one image each
        float v = 0.f;
        if (ib < B) {
            // atomicAdd(p, 0) reads coherently from L2
            float bce = atomicAdd(&g_bce, 0.f) * (1.f / (float)NTOT);
            float ws  = atomicAdd(&g_wsum[ib],  0.f);
            float in_ = atomicAdd(&g_inter[ib], 0.f);
            float un_ = atomicAdd(&g_uni[ib],   0.f);
            float qs  = atomicAdd(&g_qsum[ib],  0.f);
            float wbce = (ws * bce + 1e-8f) / (ws + 1e-8f);
            float wiou = 1.f - (in_ + 1.f + 1e-8f) / (un_ - in_ + 1.f + 1e-8f);
            float el   = 1.f - qs * (1.f / (float)NPIX);
            v = wbce + wiou + el;
        }
        #pragma unroll
        for (int o = 16; o > 0; o >>= 1) v += __shfl_xor_sync(~0u, v, o);
        if (ib == 0) out[0] = v * (1.f / (float)B);
        // reset accumulators for the next replay
        if (ib < B) {
            g_sum_t[ib] = 0.f; g_sum_p[ib] = 0.f;
            g_wsum[ib]  = 0.f; g_inter[ib] = 0.f;
            g_uni[ib]   = 0.f; g_qsum[ib]  = 0.f;
        }
        if (ib == 0) { g_bce = 0.f; g_done = 0; }
    }
}

extern "C" void kernel_launch(void* const* d_in, const int* in_sizes, int n_in,
                              void* d_out, int out_size) {
    const float* y_pred   = (const float*)d_in[0];
    const float* y_target = (const float*)d_in[1];
    float* out = (float*)d_out;

    k_statsA<<<2048, 256>>>(y_pred, y_target);
    k_hboxA<<<2048, 256>>>(y_target);
    k_passB<<<2048, 128>>>(y_pred, y_target, out);
}

// round 5
// speedup vs baseline: 1.4920x; 1.4920x over previous
#include <cuda_runtime.h>
#include <math.h>

#define B 32
#define HH 512
#define WW 512
#define NPIX (HH*WW)          // 262144
#define NTOT (B*NPIX)         // 8388608
#define KRAD 15               // box radius

// Scratch: horizontal box sums of y_target. 33.5 MB.
__device__ float g_Hsum[NTOT];

// Accumulators (zero at module load; Pass-B tail restores zeros every call)
__device__ float g_sum_t[B];
__device__ float g_sum_p[B];
__device__ float g_wsum[B];
__device__ float g_inter[B];
__device__ float g_uni[B];
__device__ float g_qsum[B];
__device__ float g_bce;
__device__ int   g_done;

__device__ __forceinline__ float fsigmoid(float x) {
    return __fdividef(1.f, 1.f + __expf(-x));
}

// -------- Pass A: horizontal box sums + per-image sum_t, sum_p, global bce ---
// 8 warps per block, one warp per row. 2048 blocks cover 16384 rows.
// Single DRAM read of T+P; writes H.
__global__ __launch_bounds__(256) void k_passA(const float* __restrict__ P,
                                               const float* __restrict__ T) {
    __shared__ __align__(16) float sIn[8][WW];
    __shared__ __align__(16) float sOut[8][WW];
    __shared__ float red[3][8];

    const int warp = threadIdx.x >> 5;
    const int lane = threadIdx.x & 31;
    const int rowg = blockIdx.x * 8 + warp;          // global row 0..16383
    const int b    = blockIdx.x >> 6;                // 64 blocks per image

    const float4* t4 = (const float4*)(T + (size_t)rowg * WW);
    const float4* p4 = (const float4*)(P + (size_t)rowg * WW);

    float lsum_t = 0.f, lsum_p = 0.f, lbce = 0.f;
    #pragma unroll
    for (int i = 0; i < 4; i++) {
        float4 tv = t4[lane + 32*i];
        float4 pv = p4[lane + 32*i];
        ((float4*)sIn[warp])[lane + 32*i] = tv;
        float ts[4] = {tv.x, tv.y, tv.z, tv.w};
        float xs[4] = {pv.x, pv.y, pv.z, pv.w};
        #pragma unroll
        for (int k = 0; k < 4; k++) {
            float t = ts[k], x = xs[k];
            lsum_t += t;
            lsum_p += fsigmoid(x);
            // stable BCE-with-logits: max(x,0) - x*t + log(1 + exp(-|x|))
            lbce   += fmaxf(x, 0.f) - x * t + __logf(1.f + __expf(-fabsf(x)));
        }
    }
    __syncwarp();

    // per-lane sliding window over 16 contiguous columns (register window,
    // reads from smem — no memory-serial chain since smem writes done above)
    const int base = lane * 16;
    float s = 0.f;
    #pragma unroll
    for (int k = base - KRAD; k <= base + KRAD; k++)
        if (k >= 0 && k < WW) s += sIn[warp][k];
    sOut[warp][base] = s;
    #pragma unroll
    for (int j = 1; j < 16; j++) {
        int ka = base + KRAD + j;
        int kr = base - KRAD - 1 + j;
        if (ka < WW) s += sIn[warp][ka];
        if (kr >= 0) s -= sIn[warp][kr];
        sOut[warp][base + j] = s;
    }
    __syncwarp();

    float4* h4 = (float4*)(g_Hsum + (size_t)rowg * WW);
    #pragma unroll
    for (int i = 0; i < 4; i++)
        h4[lane + 32*i] = ((float4*)sOut[warp])[lane + 32*i];

    #pragma unroll
    for (int o = 16; o > 0; o >>= 1) {
        lsum_t += __shfl_xor_sync(~0u, lsum_t, o);
        lsum_p += __shfl_xor_sync(~0u, lsum_p, o);
        lbce   += __shfl_xor_sync(~0u, lbce,   o);
    }
    if (lane == 0) { red[0][warp] = lsum_t; red[1][warp] = lsum_p; red[2][warp] = lbce; }
    __syncthreads();
    if (threadIdx.x == 0) {
        float a = 0.f, c = 0.f, d = 0.f;
        #pragma unroll
        for (int w = 0; w < 8; w++) { a += red[0][w]; c += red[1][w]; d += red[2][w]; }
        atomicAdd(&g_sum_t[b], a);
        atomicAdd(&g_sum_p[b], c);
        atomicAdd(&g_bce, d);
    }
}

// -------- Pass B: vertical box via SMEM-staged halo + weighted sums + E ------
// grid 2048: b = bx>>6, band = (bx>>2)&15 (32 rows), strip = bx&3 (128 cols).
// The H halo band (62 rows x 128 cols) is staged into smem with independent
// float4 loads (high MLP), then the per-column running window runs out of
// smem registersonly — removing the L2-latency serial chain.
__global__ __launch_bounds__(128) void k_passB(const float* __restrict__ P,
                                               const float* __restrict__ T,
                                               float* __restrict__ out) {
    __shared__ __align__(16) float sH[62][128];    // 31.75 KB
    __shared__ float red[4][4];
    __shared__ int s_last;

    const int bx    = blockIdx.x;
    const int b     = bx >> 6;
    const int band  = (bx >> 2) & 15;
    const int strip = bx & 3;
    const int tid   = threadIdx.x;
    const int warp  = tid >> 5, lane = tid & 31;
    const int gcol  = strip * 128 + tid;
    const int r0    = band * 32;

    const float* Hb = g_Hsum + (size_t)b * NPIX;
    const float* Tb = T + (size_t)b * NPIX;
    const float* Pb = P + (size_t)b * NPIX;

    // Stage H rows [r0-15, r0+46] for this 128-col strip. One row per warp
    // per step: 32 lanes x float4 = 128 floats. ~15 independent loads/thread.
    #pragma unroll
    for (int j = warp; j < 62; j += 4) {
        int gr = r0 - KRAD + j;
        float4 v = make_float4(0.f, 0.f, 0.f, 0.f);
        if (gr >= 0 && gr < HH)
            v = ((const float4*)(Hb + (size_t)gr * WW + strip * 128))[lane];
        ((float4*)sH[j])[lane] = v;
    }
    __syncthreads();

    const float mean_p = g_sum_p[b] * (1.f / (float)NPIX);
    const float mean_t = g_sum_t[b] * (1.f / (float)NPIX);

    // init vertical window: rows j=0..30 (global r0-15..r0+15)
    float vsum = 0.f;
    #pragma unroll
    for (int j = 0; j < 31; j++) vsum += sH[j][tid];

    float a_w = 0.f, a_i = 0.f, a_u = 0.f, a_q = 0.f;
    #pragma unroll 8
    for (int i = 0; i < 32; i++) {
        float box = vsum * (1.f / 961.f);
        float t = Tb[(size_t)(r0 + i) * WW + gcol];
        float x = Pb[(size_t)(r0 + i) * WW + gcol];
        float p = fsigmoid(x);
        float w = 1.f + 5.f * fabsf(box - t);
        a_w += w;
        a_i += p * t * w;
        a_u += (p + t) * w;
        float fp = p - mean_p;
        float ft = t - mean_t;
        float efm = __fdividef(2.f * fp * ft + 1e-8f, fp * fp + ft * ft + 1e-8f);
        float q = 1.f + efm;
        a_q += q * q * 0.25f;
        if (i < 31) vsum += sH[i + 31][tid] - sH[i][tid];
    }

    #pragma unroll
    for (int o = 16; o > 0; o >>= 1) {
        a_w += __shfl_xor_sync(~0u, a_w, o);
        a_i += __shfl_xor_sync(~0u, a_i, o);
        a_u += __shfl_xor_sync(~0u, a_u, o);
        a_q += __shfl_xor_sync(~0u, a_q, o);
    }
    if (lane == 0) { red[0][warp] = a_w; red[1][warp] = a_i; red[2][warp] = a_u; red[3][warp] = a_q; }
    __syncthreads();
    if (tid == 0) {
        float rw = 0.f, ri = 0.f, ru = 0.f, rq = 0.f;
        #pragma unroll
        for (int w = 0; w < 4; w++) { rw += red[0][w]; ri += red[1][w]; ru += red[2][w]; rq += red[3][w]; }
        atomicAdd(&g_wsum[b],  rw);
        atomicAdd(&g_inter[b], ri);
        atomicAdd(&g_uni[b],   ru);
        atomicAdd(&g_qsum[b],  rq);
        __threadfence();
        s_last = (atomicAdd(&g_done, 1) == gridDim.x - 1);
    }
    __syncthreads();

    if (s_last) {
        const int ib = tid;   // threads 0..31 handle one image each
        float v = 0.f;
        if (ib < B) {
            float bce = atomicAdd(&g_bce, 0.f) * (1.f / (float)NTOT);
            float ws  = atomicAdd(&g_wsum[ib],  0.f);
            float in_ = atomicAdd(&g_inter[ib], 0.f);
            float un_ = atomicAdd(&g_uni[ib],   0.f);
            float qs  = atomicAdd(&g_qsum[ib],  0.f);
            float wbce = (ws * bce + 1e-8f) / (ws + 1e-8f);
            float wiou = 1.f - (in_ + 1.f + 1e-8f) / (un_ - in_ + 1.f + 1e-8f);
            float el   = 1.f - qs * (1.f / (float)NPIX);
            v = wbce + wiou + el;
        }
        #pragma unroll
        for (int o = 16; o > 0; o >>= 1) v += __shfl_xor_sync(~0u, v, o);
        if (ib == 0) out[0] = v * (1.f / (float)B);
        if (ib < B) {
            g_sum_t[ib] = 0.f; g_sum_p[ib] = 0.f;
            g_wsum[ib]  = 0.f; g_inter[ib] = 0.f;
            g_uni[ib]   = 0.f; g_qsum[ib]  = 0.f;
        }
        if (ib == 0) { g_bce = 0.f; g_done = 0; }
    }
}

extern "C" void kernel_launch(void* const* d_in, const int* in_sizes, int n_in,
                              void* d_out, int out_size) {
    const float* y_pred   = (const float*)d_in[0];
    const float* y_target = (const float*)d_in[1];
    float* out = (float*)d_out;

    k_passA<<<2048, 256>>>(y_pred, y_target);
    k_passB<<<2048, 128>>>(y_pred, y_target, out);
}

// round 6
// speedup vs baseline: 3.1628x; 2.1198x over previous
#include <cuda_runtime.h>
#include <math.h>

#define B 32
#define HH 512
#define WW 512
#define NPIX (HH*WW)          // 262144
#define NTOT (B*NPIX)         // 8388608
#define KRAD 15               // box radius

// swizzle: one pad float per 16 -> stride-16 access patterns become
// stride-17 (odd) -> conflict-free across 32 banks
#define SWZ(i) ((i) + ((i) >> 4))
#define SWW 544                // 512 + 32 pad floats per row

// Scratch: horizontal box sums of y_target. 33.5 MB.
__device__ float g_Hsum[NTOT];

// Accumulators (zero at module load; Pass-B tail restores zeros every call)
__device__ float g_sum_t[B];
__device__ float g_sum_p[B];
__device__ float g_wsum[B];
__device__ float g_inter[B];
__device__ float g_uni[B];
__device__ float g_qsum[B];
__device__ float g_bce;
__device__ int   g_done;

__device__ __forceinline__ float fsigmoid(float x) {
    return __fdividef(1.f, 1.f + __expf(-x));
}

// -------- Pass A: horizontal box sums + per-image sum_t, sum_p, global bce ---
// 8 warps per block, one warp per row. 2048 blocks cover 16384 rows.
__global__ __launch_bounds__(256) void k_passA(const float* __restrict__ P,
                                               const float* __restrict__ T) {
    __shared__ float sIn[8][SWW];    // swizzled; reused as output staging
    __shared__ float red[3][8];

    const int warp = threadIdx.x >> 5;
    const int lane = threadIdx.x & 31;
    const int rowg = blockIdx.x * 8 + warp;          // global row 0..16383
    const int b    = blockIdx.x >> 6;                // 64 blocks per image

    const float4* t4 = (const float4*)(T + (size_t)rowg * WW);
    const float4* p4 = (const float4*)(P + (size_t)rowg * WW);

    float lsum_t = 0.f, lsum_p = 0.f, lbce = 0.f;
    #pragma unroll
    for (int i = 0; i < 4; i++) {
        float4 tv = t4[lane + 32*i];
        float4 pv = p4[lane + 32*i];
        const int c0 = 4*lane + 128*i;
        sIn[warp][SWZ(c0+0)] = tv.x;
        sIn[warp][SWZ(c0+1)] = tv.y;
        sIn[warp][SWZ(c0+2)] = tv.z;
        sIn[warp][SWZ(c0+3)] = tv.w;
        float ts[4] = {tv.x, tv.y, tv.z, tv.w};
        float xs[4] = {pv.x, pv.y, pv.z, pv.w};
        #pragma unroll
        for (int k = 0; k < 4; k++) {
            float t = ts[k], x = xs[k];
            float p = fsigmoid(x);
            lsum_t += t;
            lsum_p += p;
            // bce = max(x,0) - x*t + log1p(exp(-|x|)); log1p(exp(-|x|)) = -log(sigmoid(|x|))
            float sabs = (x >= 0.f) ? p : (1.f - p);
            lbce += fmaxf(x, 0.f) - x * t - __logf(sabs);
        }
    }
    __syncwarp();

    // per-lane sliding window over 16 contiguous columns, conflict-free reads
    const int base = lane * 16;
    float h[16];
    float s = 0.f;
    #pragma unroll
    for (int kk = 0; kk < 31; kk++) {
        int k = base - KRAD + kk;
        if (k >= 0 && k < WW) s += sIn[warp][SWZ(k)];
    }
    h[0] = s;
    #pragma unroll
    for (int j = 1; j < 16; j++) {
        int ka = base + KRAD + j;
        int kr = base - KRAD - 1 + j;
        if (ka < WW) s += sIn[warp][SWZ(ka)];
        if (kr >= 0) s -= sIn[warp][SWZ(kr)];
        h[j] = s;
    }
    __syncwarp();

    // stage outputs back into (reused) swizzled smem, then coalesced float4 STG
    #pragma unroll
    for (int j = 0; j < 16; j++)
        sIn[warp][SWZ(base + j)] = h[j];
    __syncwarp();

    float4* h4 = (float4*)(g_Hsum + (size_t)rowg * WW);
    #pragma unroll
    for (int i = 0; i < 4; i++) {
        const int c0 = 4*lane + 128*i;
        float4 o;
        o.x = sIn[warp][SWZ(c0+0)];
        o.y = sIn[warp][SWZ(c0+1)];
        o.z = sIn[warp][SWZ(c0+2)];
        o.w = sIn[warp][SWZ(c0+3)];
        h4[lane + 32*i] = o;
    }

    #pragma unroll
    for (int o = 16; o > 0; o >>= 1) {
        lsum_t += __shfl_xor_sync(~0u, lsum_t, o);
        lsum_p += __shfl_xor_sync(~0u, lsum_p, o);
        lbce   += __shfl_xor_sync(~0u, lbce,   o);
    }
    if (lane == 0) { red[0][warp] = lsum_t; red[1][warp] = lsum_p; red[2][warp] = lbce; }
    __syncthreads();
    if (threadIdx.x == 0) {
        float a = 0.f, c = 0.f, d = 0.f;
        #pragma unroll
        for (int w = 0; w < 8; w++) { a += red[0][w]; c += red[1][w]; d += red[2][w]; }
        atomicAdd(&g_sum_t[b], a);
        atomicAdd(&g_sum_p[b], c);
        atomicAdd(&g_bce, d);
    }
}

// -------- Pass B: vertical box via SMEM-staged halo + weighted sums + E ------
// grid 2048: b = bx>>6, band = (bx>>2)&15 (32 rows), strip = bx&3 (128 cols).
__global__ __launch_bounds__(128) void k_passB(const float* __restrict__ P,
                                               const float* __restrict__ T,
                                               float* __restrict__ out) {
    __shared__ __align__(16) float sH[62][128];    // 31.75 KB
    __shared__ float red[4][4];
    __shared__ int s_last;

    const int bx    = blockIdx.x;
    const int b     = bx >> 6;
    const int band  = (bx >> 2) & 15;
    const int strip = bx & 3;
    const int tid   = threadIdx.x;
    const int warp  = tid >> 5, lane = tid & 31;
    const int gcol  = strip * 128 + tid;
    const int r0    = band * 32;

    const float* Hb = g_Hsum + (size_t)b * NPIX;
    const float* Tb = T + (size_t)b * NPIX;
    const float* Pb = P + (size_t)b * NPIX;

    // Stage H rows [r0-15, r0+46] for this strip: independent float4 loads.
    #pragma unroll
    for (int j = warp; j < 62; j += 4) {
        int gr = r0 - KRAD + j;
        float4 v = make_float4(0.f, 0.f, 0.f, 0.f);
        if (gr >= 0 && gr < HH)
            v = ((const float4*)(Hb + (size_t)gr * WW + strip * 128))[lane];
        ((float4*)sH[j])[lane] = v;
    }
    __syncthreads();

    const float mean_p = g_sum_p[b] * (1.f / (float)NPIX);
    const float mean_t = g_sum_t[b] * (1.f / (float)NPIX);

    float vsum = 0.f;
    #pragma unroll
    for (int j = 0; j < 31; j++) vsum += sH[j][tid];

    float a_w = 0.f, a_i = 0.f, a_u = 0.f, a_q = 0.f;
    #pragma unroll 8
    for (int i = 0; i < 32; i++) {
        float box = vsum * (1.f / 961.f);
        float t = Tb[(size_t)(r0 + i) * WW + gcol];
        float x = Pb[(size_t)(r0 + i) * WW + gcol];
        float p = fsigmoid(x);
        float w = 1.f + 5.f * fabsf(box - t);
        a_w += w;
        a_i += p * t * w;
        a_u += (p + t) * w;
        float fp = p - mean_p;
        float ft = t - mean_t;
        float efm = __fdividef(2.f * fp * ft + 1e-8f, fp * fp + ft * ft + 1e-8f);
        float q = 1.f + efm;
        a_q += q * q * 0.25f;
        if (i < 31) vsum += sH[i + 31][tid] - sH[i][tid];
    }

    #pragma unroll
    for (int o = 16; o > 0; o >>= 1) {
        a_w += __shfl_xor_sync(~0u, a_w, o);
        a_i += __shfl_xor_sync(~0u, a_i, o);
        a_u += __shfl_xor_sync(~0u, a_u, o);
        a_q += __shfl_xor_sync(~0u, a_q, o);
    }
    if (lane == 0) { red[0][warp] = a_w; red[1][warp] = a_i; red[2][warp] = a_u; red[3][warp] = a_q; }
    __syncthreads();
    if (tid == 0) {
        float rw = 0.f, ri = 0.f, ru = 0.f, rq = 0.f;
        #pragma unroll
        for (int w = 0; w < 4; w++) { rw += red[0][w]; ri += red[1][w]; ru += red[2][w]; rq += red[3][w]; }
        atomicAdd(&g_wsum[b],  rw);
        atomicAdd(&g_inter[b], ri);
        atomicAdd(&g_uni[b],   ru);
        atomicAdd(&g_qsum[b],  rq);
        __threadfence();
        s_last = (atomicAdd(&g_done, 1) == gridDim.x - 1);
    }
    __syncthreads();

    if (s_last) {
        const int ib = tid;   // threads 0..31 handle one image each
        float v = 0.f;
        if (ib < B) {
            float bce = atomicAdd(&g_bce, 0.f) * (1.f / (float)NTOT);
            float ws  = atomicAdd(&g_wsum[ib],  0.f);
            float in_ = atomicAdd(&g_inter[ib], 0.f);
            float un_ = atomicAdd(&g_uni[ib],   0.f);
            float qs  = atomicAdd(&g_qsum[ib],  0.f);
            float wbce = (ws * bce + 1e-8f) / (ws + 1e-8f);
            float wiou = 1.f - (in_ + 1.f + 1e-8f) / (un_ - in_ + 1.f + 1e-8f);
            float el   = 1.f - qs * (1.f / (float)NPIX);
            v = wbce + wiou + el;
        }
        #pragma unroll
        for (int o = 16; o > 0; o >>= 1) v += __shfl_xor_sync(~0u, v, o);
        if (ib == 0) out[0] = v * (1.f / (float)B);
        if (ib < B) {
            g_sum_t[ib] = 0.f; g_sum_p[ib] = 0.f;
            g_wsum[ib]  = 0.f; g_inter[ib] = 0.f;
            g_uni[ib]   = 0.f; g_qsum[ib]  = 0.f;
        }
        if (ib == 0) { g_bce = 0.f; g_done = 0; }
    }
}

extern "C" void kernel_launch(void* const* d_in, const int* in_sizes, int n_in,
                              void* d_out, int out_size) {
    const float* y_pred   = (const float*)d_in[0];
    const float* y_target = (const float*)d_in[1];
    float* out = (float*)d_out;

    k_passA<<<2048, 256>>>(y_pred, y_target);
    k_passB<<<2048, 128>>>(y_pred, y_target, out);
}